// round 7
// baseline (speedup 1.0000x reference)
#include <cuda_runtime.h>
#include <cuda_bf16.h>

// VoxelCollisionCost: B=1024, H=32, L=8 links, S=8 spheres, 256^3 SDF grid.
// One thread per (b,h,l); 8 lanes (l fastest) share one (b,h) -> shfl reduce.
// Fully warp-autonomous: each warp stages its own 4 bh-groups of pose data and
// its own repacked sphere-model copy; NO __syncthreads anywhere -> warps
// desynchronize and pipeline each other's memory latency.

#define GRID_N   256
#define N_LINKS  8
#define N_SPH    8

__global__ void __launch_bounds__(256, 8) vox_cost_kernel(
    const float* __restrict__ link_pos,   // [B,H,8,3]
    const float* __restrict__ link_rot,   // [B,H,8,3,3]
    const float* __restrict__ sph_ctr,    // [8,8,3]
    const float* __restrict__ sph_rad,    // [8,8]
    const float* __restrict__ sdf,        // [256,256,256]
    const float* __restrict__ weight,     // [1]
    float* __restrict__ out)              // [B,H]
{
    // Per-warp private regions (8 warps/block):
    //  s_model: [warp][l][9 float4] (stride 9 pads banks; slot s holds {c,r})
    //  s_stage: [warp][96 float4]   raw pos(24) + rot(72) float4 copy
    __shared__ float4 s_model[8 * 72];    //  9216 B
    __shared__ float4 s_stage[8 * 96];    // 12288 B

    const int tid  = threadIdx.x;
    const int w    = tid >> 5;            // warp id 0..7
    const int lane = tid & 31;

    float4* mdl = s_model + w * 72;
    float4* stg = s_stage + w * 96;

    // ---- per-warp model repack: 2 (l,s) pairs per lane -> {cx,cy,cz,r} ----
    #pragma unroll
    for (int rep = 0; rep < 2; rep++) {
        const int p = lane + rep * 32;          // 0..63 : p = l*8+s
        const int pl = p >> 3, ps = p & 7;
        float4 m;
        m.x = __ldg(sph_ctr + 3 * p + 0);
        m.y = __ldg(sph_ctr + 3 * p + 1);
        m.z = __ldg(sph_ctr + 3 * p + 2);
        m.w = __ldg(sph_rad + p);
        mdl[pl * 9 + ps] = m;
    }

    // ---- per-warp pose staging: this warp's 4 bh-groups, 3 float4/lane ----
    // global bh base = blockIdx.x*32 + w*4
    const float4* posv = reinterpret_cast<const float4*>(link_pos)
                       + (size_t)blockIdx.x * 192 + w * 24;   // 24 float4
    const float4* rotv = reinterpret_cast<const float4*>(link_rot)
                       + (size_t)blockIdx.x * 576 + w * 72;   // 72 float4
    #pragma unroll
    for (int k = 0; k < 3; k++) {
        const int j = lane + k * 32;             // 0..95
        stg[j] = (j < 24) ? __ldg(posv + j) : __ldg(rotv + (j - 24));
    }
    __syncwarp();

    const int bh = lane >> 3;      // warp-local bh group 0..3
    const int l  = lane & 7;       // link index

    // Conflict-free scalar reads (bank map (8bh+9l) mod 32 is a bijection).
    const float* S = reinterpret_cast<const float*>(stg);
    const float* R = S + 96 + bh * 72 + l * 9;   // rot floats start at 24 f4
    const float* P = S +      bh * 24 + l * 3;
    const float r00 = R[0], r01 = R[1], r02 = R[2];
    const float r10 = R[3], r11 = R[4], r12 = R[5];
    const float r20 = R[6], r21 = R[7], r22 = R[8];
    const float px = P[0], py = P[1], pz = P[2];

    // ---- 8 voxel indices (independent -> batched gathers) ----
    int   lin[N_SPH];
    float rad[N_SPH];
    #pragma unroll
    for (int s = 0; s < N_SPH; s++) {
        const float4 m = mdl[l * 9 + s];         // conflict-free LDS.128
        rad[s] = m.w;
        const float x = fmaf(r00, m.x, fmaf(r01, m.y, fmaf(r02, m.z, px)));
        const float y = fmaf(r10, m.x, fmaf(r11, m.y, fmaf(r12, m.z, py)));
        const float z = fmaf(r20, m.x, fmaf(r21, m.y, fmaf(r22, m.z, pz)));
        // exact reference semantics: floor((p + 1.28) / 0.01), rn-division
        int ix = (int)floorf(__fdiv_rn(x + 1.28f, 0.01f));
        int iy = (int)floorf(__fdiv_rn(y + 1.28f, 0.01f));
        int iz = (int)floorf(__fdiv_rn(z + 1.28f, 0.01f));
        ix = min(max(ix, 0), GRID_N - 1);
        iy = min(max(iy, 0), GRID_N - 1);
        iz = min(max(iz, 0), GRID_N - 1);
        lin[s] = (ix << 16) | (iy << 8) | iz;
    }

    // ---- gather + penetration; loads batch back-to-back ----
    float pen[N_SPH];
    #pragma unroll
    for (int s = 0; s < N_SPH; s++)
        pen[s] = rad[s] - __ldg(sdf + lin[s]);

    float m = pen[0];
    #pragma unroll
    for (int s = 1; s < N_SPH; s++) m = fmaxf(m, pen[s]);

    // threshold + clip + /0.25 (== *4 exactly)
    float res = fminf(fmaxf(m - 0.01f, 0.0f), 0.5f) * 4.0f;

    // sum over 8 links (lanes l..l+7 share (b,h))
    res += __shfl_xor_sync(0xffffffffu, res, 1);
    res += __shfl_xor_sync(0xffffffffu, res, 2);
    res += __shfl_xor_sync(0xffffffffu, res, 4);

    if (l == 0)
        out[blockIdx.x * 32 + w * 4 + bh] = __ldg(weight) * res;
}

extern "C" void kernel_launch(void* const* d_in, const int* in_sizes, int n_in,
                              void* d_out, int out_size) {
    const float* link_pos = (const float*)d_in[0];
    const float* link_rot = (const float*)d_in[1];
    const float* sph_ctr  = (const float*)d_in[2];
    const float* sph_rad  = (const float*)d_in[3];
    const float* sdf      = (const float*)d_in[4];
    const float* weight   = (const float*)d_in[5];
    float* out = (float*)d_out;

    const int n_bh   = out_size;               // B*H = 32768
    const int blocks = (n_bh * N_LINKS) / 256; // 1024 blocks of 256 threads

    vox_cost_kernel<<<blocks, 256>>>(link_pos, link_rot, sph_ctr, sph_rad,
                                     sdf, weight, out);
}

// round 9
// speedup vs baseline: 1.2243x; 1.2243x over previous
#include <cuda_runtime.h>
#include <cuda_bf16.h>

// VoxelCollisionCost: B=1024, H=32, L=8 links, S=8 spheres, 256^3 SDF grid.
// One thread per (b,h,l); 8 lanes (l fastest) share one (b,h) -> shfl reduce.
//
// Anti-convoy structure:
//  1) pose LDG.128s issued into registers FIRST (DRAM stream starts at cycle 0)
//  2) block-level model repack (cheap, L1-hot) under the only __syncthreads,
//     which overlaps with the in-flight pose loads
//  3) poses -> per-warp smem slice, __syncwarp only -> warps desync into
//     the gather phase instead of bursting together.

#define GRID_N   256
#define N_LINKS  8
#define N_SPH    8

__global__ void __launch_bounds__(256) vox_cost_kernel(
    const float* __restrict__ link_pos,   // [B,H,8,3]
    const float* __restrict__ link_rot,   // [B,H,8,3,3]
    const float* __restrict__ sph_ctr,    // [8,8,3]
    const float* __restrict__ sph_rad,    // [8,8]
    const float* __restrict__ sdf,        // [256,256,256]
    const float* __restrict__ weight,     // [1]
    float* __restrict__ out)              // [B,H]
{
    // Packed model: [l][9] float4 (stride 9 -> conflict-free LDS.128),
    // slot s holds {cx, cy, cz, r}.
    __shared__ float4 s_model[N_LINKS * 9];        // 1152 B
    // Per-warp pose slice: 96 float4 (24 pos + 72 rot)
    __shared__ float4 s_stage[8 * 96];             // 12288 B

    const int tid  = threadIdx.x;
    const int w    = tid >> 5;
    const int lane = tid & 31;

    // ---- 1) issue this warp's pose loads into registers immediately ----
    const float4* posv = reinterpret_cast<const float4*>(link_pos)
                       + (size_t)blockIdx.x * 192 + w * 24;
    const float4* rotv = reinterpret_cast<const float4*>(link_rot)
                       + (size_t)blockIdx.x * 576 + w * 72;
    float4 v0, v1, v2;
    {
        const int j0 = lane, j1 = lane + 32, j2 = lane + 64;
        v0 = (j0 < 24) ? __ldg(posv + j0) : __ldg(rotv + (j0 - 24));
        v1 = __ldg(rotv + (j1 - 24));
        v2 = __ldg(rotv + (j2 - 24));
    }

    // ---- 2) block-level model repack (overlaps with pose loads) ----
    if (tid < 64) {
        const int pl = tid >> 3, ps = tid & 7;
        float4 m;
        m.x = __ldg(sph_ctr + 3 * tid + 0);
        m.y = __ldg(sph_ctr + 3 * tid + 1);
        m.z = __ldg(sph_ctr + 3 * tid + 2);
        m.w = __ldg(sph_rad + tid);
        s_model[pl * 9 + ps] = m;
    }
    __syncthreads();   // guards only s_model; pose loads still in flight

    // ---- 3) poses -> per-warp smem slice ----
    float4* stg = s_stage + w * 96;
    stg[lane]      = v0;
    stg[lane + 32] = v1;
    stg[lane + 64] = v2;
    __syncwarp();

    const int bh = lane >> 3;      // warp-local bh group 0..3
    const int l  = lane & 7;       // link index

    // Conflict-free scalar reads (bank map is a bijection across the warp).
    const float* S = reinterpret_cast<const float*>(stg);
    const float* R = S + 96 + bh * 72 + l * 9;
    const float* P = S +      bh * 24 + l * 3;
    const float r00 = R[0], r01 = R[1], r02 = R[2];
    const float r10 = R[3], r11 = R[4], r12 = R[5];
    const float r20 = R[6], r21 = R[7], r22 = R[8];
    const float px = P[0], py = P[1], pz = P[2];

    // ---- 8 voxel indices (independent -> batched gathers) ----
    int   lin[N_SPH];
    float rad[N_SPH];
    #pragma unroll
    for (int s = 0; s < N_SPH; s++) {
        const float4 m = s_model[l * 9 + s];     // conflict-free LDS.128
        rad[s] = m.w;
        const float x = fmaf(r00, m.x, fmaf(r01, m.y, fmaf(r02, m.z, px)));
        const float y = fmaf(r10, m.x, fmaf(r11, m.y, fmaf(r12, m.z, py)));
        const float z = fmaf(r20, m.x, fmaf(r21, m.y, fmaf(r22, m.z, pz)));
        // exact reference semantics: floor((p + 1.28) / 0.01), rn-division
        int ix = (int)floorf(__fdiv_rn(x + 1.28f, 0.01f));
        int iy = (int)floorf(__fdiv_rn(y + 1.28f, 0.01f));
        int iz = (int)floorf(__fdiv_rn(z + 1.28f, 0.01f));
        ix = min(max(ix, 0), GRID_N - 1);
        iy = min(max(iy, 0), GRID_N - 1);
        iz = min(max(iz, 0), GRID_N - 1);
        lin[s] = (ix << 16) | (iy << 8) | iz;
    }

    // ---- gather + penetration; loads batch back-to-back ----
    float pen[N_SPH];
    #pragma unroll
    for (int s = 0; s < N_SPH; s++)
        pen[s] = rad[s] - __ldg(sdf + lin[s]);

    float m = pen[0];
    #pragma unroll
    for (int s = 1; s < N_SPH; s++) m = fmaxf(m, pen[s]);

    // threshold + clip + /0.25 (== *4 exactly)
    float res = fminf(fmaxf(m - 0.01f, 0.0f), 0.5f) * 4.0f;

    // sum over 8 links (lanes l..l+7 share (b,h))
    res += __shfl_xor_sync(0xffffffffu, res, 1);
    res += __shfl_xor_sync(0xffffffffu, res, 2);
    res += __shfl_xor_sync(0xffffffffu, res, 4);

    if (l == 0)
        out[blockIdx.x * 32 + w * 4 + bh] = __ldg(weight) * res;
}

extern "C" void kernel_launch(void* const* d_in, const int* in_sizes, int n_in,
                              void* d_out, int out_size) {
    const float* link_pos = (const float*)d_in[0];
    const float* link_rot = (const float*)d_in[1];
    const float* sph_ctr  = (const float*)d_in[2];
    const float* sph_rad  = (const float*)d_in[3];
    const float* sdf      = (const float*)d_in[4];
    const float* weight   = (const float*)d_in[5];
    float* out = (float*)d_out;

    const int n_bh   = out_size;               // B*H = 32768
    const int blocks = (n_bh * N_LINKS) / 256; // 1024 blocks of 256 threads

    vox_cost_kernel<<<blocks, 256>>>(link_pos, link_rot, sph_ctr, sph_rad,
                                     sdf, weight, out);
}

// round 13
// speedup vs baseline: 1.3877x; 1.1335x over previous
#include <cuda_runtime.h>
#include <cuda_bf16.h>

// VoxelCollisionCost: B=1024, H=32, L=8 links, S=8 spheres, 256^3 SDF grid.
// ILP=2 at full occupancy: each thread does TWO (b,h) units -> 16 gathers in
// flight, with registers managed (gathers issued inside the index loop, radii
// re-read from smem at consume time) so <=48 regs keeps 5 blocks/SM.

#define GRID_N   256
#define N_LINKS  8
#define N_SPH    8
#define BH_PER_BLOCK 64

__global__ void __launch_bounds__(256, 5) vox_cost_kernel(
    const float* __restrict__ link_pos,   // [B,H,8,3]
    const float* __restrict__ link_rot,   // [B,H,8,3,3]
    const float* __restrict__ sph_ctr,    // [8,8,3]
    const float* __restrict__ sph_rad,    // [8,8]
    const float* __restrict__ sdf,        // [256,256,256]
    const float* __restrict__ weight,     // [1]
    float* __restrict__ out)              // [B,H]
{
    // Packed model [l][9] float4, slot s = {cx,cy,cz,r}; stride 9 -> LDS.128
    // conflict-free across the warp, and .w re-reads broadcast.
    __shared__ float4 s_model[N_LINKS * 9];
    // 64 bh-groups: pos 1536 floats + rot 4608 floats
    __shared__ float s_stage[6144];

    const int tid = threadIdx.x;

    // ---- stage poses: 6 float4 per thread, fully coalesced ----
    const float4* posv = reinterpret_cast<const float4*>(link_pos) + (size_t)blockIdx.x * 384;
    const float4* rotv = reinterpret_cast<const float4*>(link_rot) + (size_t)blockIdx.x * 1152;
    float4* s4 = reinterpret_cast<float4*>(s_stage);
    #pragma unroll
    for (int k = 0; k < 6; k++) {
        const int j = tid + k * 256;
        s4[j] = (j < 384) ? __ldg(posv + j) : __ldg(rotv + (j - 384));
    }

    // ---- model repack (overlaps with staging loads) ----
    if (tid < 64) {
        const int pl = tid >> 3, ps = tid & 7;
        float4 m;
        m.x = __ldg(sph_ctr + 3 * tid + 0);
        m.y = __ldg(sph_ctr + 3 * tid + 1);
        m.z = __ldg(sph_ctr + 3 * tid + 2);
        m.w = __ldg(sph_rad + tid);
        s_model[pl * 9 + ps] = m;
    }
    __syncthreads();

    const int lbh = tid >> 3;      // unit A bh: 0..31 (unit B: +32)
    const int l   = tid & 7;       // link index
    const float* S = s_stage;

    // ---- unit A: compute index AND issue gather per sphere (lin dies fast) ----
    float gA[N_SPH], gB[N_SPH];
    {
        const float* R = S + 1536 + lbh * 72 + l * 9;
        const float* P = S +        lbh * 24 + l * 3;
        const float r00 = R[0], r01 = R[1], r02 = R[2];
        const float r10 = R[3], r11 = R[4], r12 = R[5];
        const float r20 = R[6], r21 = R[7], r22 = R[8];
        const float px = P[0], py = P[1], pz = P[2];
        #pragma unroll
        for (int s = 0; s < N_SPH; s++) {
            const float4 m = s_model[l * 9 + s];
            const float x = fmaf(r00, m.x, fmaf(r01, m.y, fmaf(r02, m.z, px)));
            const float y = fmaf(r10, m.x, fmaf(r11, m.y, fmaf(r12, m.z, py)));
            const float z = fmaf(r20, m.x, fmaf(r21, m.y, fmaf(r22, m.z, pz)));
            int ix = (int)floorf(__fdiv_rn(x + 1.28f, 0.01f));
            int iy = (int)floorf(__fdiv_rn(y + 1.28f, 0.01f));
            int iz = (int)floorf(__fdiv_rn(z + 1.28f, 0.01f));
            ix = min(max(ix, 0), GRID_N - 1);
            iy = min(max(iy, 0), GRID_N - 1);
            iz = min(max(iz, 0), GRID_N - 1);
            gA[s] = __ldg(sdf + ((ix << 16) | (iy << 8) | iz));
        }
    }

    // ---- unit B: same, while unit A's 8 gathers are in flight ----
    {
        const int bh = lbh + 32;
        const float* R = S + 1536 + bh * 72 + l * 9;
        const float* P = S +        bh * 24 + l * 3;
        const float r00 = R[0], r01 = R[1], r02 = R[2];
        const float r10 = R[3], r11 = R[4], r12 = R[5];
        const float r20 = R[6], r21 = R[7], r22 = R[8];
        const float px = P[0], py = P[1], pz = P[2];
        #pragma unroll
        for (int s = 0; s < N_SPH; s++) {
            const float4 m = s_model[l * 9 + s];
            const float x = fmaf(r00, m.x, fmaf(r01, m.y, fmaf(r02, m.z, px)));
            const float y = fmaf(r10, m.x, fmaf(r11, m.y, fmaf(r12, m.z, py)));
            const float z = fmaf(r20, m.x, fmaf(r21, m.y, fmaf(r22, m.z, pz)));
            int ix = (int)floorf(__fdiv_rn(x + 1.28f, 0.01f));
            int iy = (int)floorf(__fdiv_rn(y + 1.28f, 0.01f));
            int iz = (int)floorf(__fdiv_rn(z + 1.28f, 0.01f));
            ix = min(max(ix, 0), GRID_N - 1);
            iy = min(max(iy, 0), GRID_N - 1);
            iz = min(max(iz, 0), GRID_N - 1);
            gB[s] = __ldg(sdf + ((ix << 16) | (iy << 8) | iz));
        }
    }

    // ---- consume: radius re-read from smem (broadcast, conflict-free) ----
    const float* mw = reinterpret_cast<const float*>(s_model) + l * 36 + 3;
    float mA = mw[0] - gA[0];
    float mB = mw[0] - gB[0];
    #pragma unroll
    for (int s = 1; s < N_SPH; s++) {
        mA = fmaxf(mA, mw[s * 4] - gA[s]);
        mB = fmaxf(mB, mw[s * 4] - gB[s]);
    }

    // threshold + clip + /0.25 (== *4 exactly)
    float resA = fminf(fmaxf(mA - 0.01f, 0.0f), 0.5f) * 4.0f;
    float resB = fminf(fmaxf(mB - 0.01f, 0.0f), 0.5f) * 4.0f;

    // sum over 8 links
    #pragma unroll
    for (int d = 1; d <= 4; d <<= 1) {
        resA += __shfl_xor_sync(0xffffffffu, resA, d);
        resB += __shfl_xor_sync(0xffffffffu, resB, d);
    }

    if (l == 0) {
        const float w = __ldg(weight);
        const int base = blockIdx.x * BH_PER_BLOCK + lbh;
        out[base]      = w * resA;
        out[base + 32] = w * resB;
    }
}

extern "C" void kernel_launch(void* const* d_in, const int* in_sizes, int n_in,
                              void* d_out, int out_size) {
    const float* link_pos = (const float*)d_in[0];
    const float* link_rot = (const float*)d_in[1];
    const float* sph_ctr  = (const float*)d_in[2];
    const float* sph_rad  = (const float*)d_in[3];
    const float* sdf      = (const float*)d_in[4];
    const float* weight   = (const float*)d_in[5];
    float* out = (float*)d_out;

    const int n_bh   = out_size;               // B*H = 32768
    const int blocks = n_bh / BH_PER_BLOCK;    // 512 blocks of 256 threads

    vox_cost_kernel<<<blocks, 256>>>(link_pos, link_rot, sph_ctr, sph_rad,
                                     sdf, weight, out);
}